// round 9
// baseline (speedup 1.0000x reference)
#include <cuda_runtime.h>
#include <cuda_fp16.h>
#include <cstdint>

// out = ReLU(LayerNorm(emb[:, :, :256] @ W_enc + b_enc) * gamma + beta)
// (reference kNN/gather path is a provable no-op: pooled == embeddings)
//
// R9: fp16 mma.sync, 1024-thread CTAs (32 warps, warp tile 16x64, 32 f32 acc
// per thread -> 64-reg cap -> 32 warps/SM instead of 16). Streaming epilogue.

#define KDIM    256
#define NDIM    512
#define DROW    512
#define BM      64
#define THREADS 1024
#define NSTAGE  8           // K / 32
#define LN_EPS  1e-5f

typedef uint32_t u32;

// prepped W: [n][k] fp16 (256 KB, L2-resident)
__device__ __half g_Wh[NDIM * KDIM];

// ---- smem layout (bytes) ----
// A [64][256] fp16 swizzled (row stride 512B) : 0     .. 32767
// B ring: 3 stages x 32KB (512 n x 64B)       : 32768 .. 131071
// epilogue reuses [0..133119] as h[64][520] f32
#define SM_B    32768
#define SMEM_TOTAL 133120
#define HSTRIDE 520

__device__ __forceinline__ u32 smem_u32(const void* p) {
    u32 a;
    asm("{ .reg .u64 t; cvta.to.shared.u64 t, %1; cvt.u32.u64 %0, t; }" : "=r"(a) : "l"(p));
    return a;
}
__device__ __forceinline__ void cp16(u32 dst, const void* src) {
    asm volatile("cp.async.cg.shared.global [%0], [%1], 16;" :: "r"(dst), "l"(src));
}
__device__ __forceinline__ void cp_commit() { asm volatile("cp.async.commit_group;"); }
template <int N>
__device__ __forceinline__ void cp_wait() { asm volatile("cp.async.wait_group %0;" :: "n"(N)); }

__device__ __forceinline__ void ldsm4(u32* r, u32 addr) {
    asm volatile("ldmatrix.sync.aligned.m8n8.x4.shared.b16 {%0,%1,%2,%3}, [%4];"
                 : "=r"(r[0]), "=r"(r[1]), "=r"(r[2]), "=r"(r[3]) : "r"(addr));
}
__device__ __forceinline__ void mma16816(float* d, const u32* a, const u32* b) {
    asm volatile(
        "mma.sync.aligned.m16n8k16.row.col.f32.f16.f16.f32 "
        "{%0,%1,%2,%3}, {%4,%5,%6,%7}, {%8,%9}, {%0,%1,%2,%3};"
        : "+f"(d[0]), "+f"(d[1]), "+f"(d[2]), "+f"(d[3])
        : "r"(a[0]), "r"(a[1]), "r"(a[2]), "r"(a[3]), "r"(b[0]), "r"(b[1]));
}

// ---------------- prep: W [k][n] f32 -> g_Wh [n][k] fp16 ----------------
__global__ void prep_w(const float* __restrict__ W) {
    const int idx = blockIdx.x * blockDim.x + threadIdx.x;   // 0..32767
    const int n  = idx & 511;
    const int k4 = idx >> 9;                                  // 0..63
    unsigned short h[4];
    #pragma unroll
    for (int e = 0; e < 4; e++) {
        const float w = W[(size_t)(k4 * 4 + e) * NDIM + n];   // coalesced over n
        h[e] = __half_as_ushort(__float2half_rn(w));
    }
    *(uint2*)&g_Wh[(size_t)n * KDIM + k4 * 4] =
        make_uint2((u32)h[0] | ((u32)h[1] << 16), (u32)h[2] | ((u32)h[3] << 16));
}

// ---------------- main fused GEMM + LN + ReLU ----------------
__global__ __launch_bounds__(THREADS, 1)
void gemm_ln_mma(const float* __restrict__ emb,
                 const float* __restrict__ bias,
                 const float* __restrict__ gamma,
                 const float* __restrict__ beta,
                 float* __restrict__ out) {
    extern __shared__ char smem[];
    const u32 sb   = smem_u32(smem);
    const int tid  = threadIdx.x;
    const int lane = tid & 31;
    const int w    = tid >> 5;       // 32 warps
    const int wr   = w >> 3;         // 0..3 : row block of 16
    const int wc   = w & 7;          // 0..7 : col block of 64
    const int m0   = blockIdx.x * BM;

    // ---- B stage loader: 2048 x 16B chunks (512 n x 4 k-quarters), 2/thread ----
    auto cpB = [&](int s) {
        const u32 bbase = sb + SM_B + (s % 3) * 32768;
        #pragma unroll
        for (int j = 0; j < 2; j++) {
            const int i  = tid + THREADS * j;
            const int n  = i >> 2;
            const int cb = i & 3;    // 16B chunk = 8 k-values within the k32 stage
            cp16(bbase + n * 64 + (((u32)cb ^ ((n >> 1) & 3)) << 4),
                 (const char*)g_Wh + (size_t)n * 512 + s * 64 + cb * 16);
        }
    };

    cpB(0); cp_commit();
    cpB(1); cp_commit();

    // ---- A: load 64x256 f32, convert to fp16 into swizzled smem ----
    #pragma unroll
    for (int i = 0; i < 4; i++) {
        const int f   = tid + THREADS * i;    // float4 index, 4096 total
        const int row = f >> 6;
        const int q   = f & 63;               // float4 within row (k = 4q)
        const float4 v = *(const float4*)&emb[(size_t)(m0 + row) * DROW + q * 4];
        const unsigned short h0 = __half_as_ushort(__float2half_rn(v.x));
        const unsigned short h1 = __half_as_ushort(__float2half_rn(v.y));
        const unsigned short h2 = __half_as_ushort(__float2half_rn(v.z));
        const unsigned short h3 = __half_as_ushort(__float2half_rn(v.w));
        const u32 addr = sb + row * 512 + ((((u32)(q >> 1)) ^ (row & 7)) << 4) + (q & 1) * 8;
        asm volatile("st.shared.v2.b32 [%0], {%1, %2};" :: "r"(addr),
                     "r"((u32)h0 | ((u32)h1 << 16)), "r"((u32)h2 | ((u32)h3 << 16)));
    }

    // ---- per-lane ldmatrix geometry (warp tile 16x64) ----
    const int a_row  = wr * 16 + ((lane >> 3) & 1) * 8 + (lane & 7);
    const int a_khalf = lane >> 4;
    u32 offB[4];
    #pragma unroll
    for (int p = 0; p < 4; p++) {
        const int n  = wc * 64 + p * 16 + ((lane >> 4) & 1) * 8 + (lane & 7);
        const int cb = (lane >> 3) & 1;
        offB[p] = n * 64 + (((u32)cb ^ ((n >> 1) & 3)) << 4);
    }

    float d[8][4];
    #pragma unroll
    for (int j = 0; j < 8; j++)
        #pragma unroll
        for (int e = 0; e < 4; e++) d[j][e] = 0.0f;

    // ---- mainloop: 8 k32-stages, 3-deep ring, prefetch distance 2 ----
    #pragma unroll 1
    for (int s = 0; s < NSTAGE; s++) {
        if (s < NSTAGE - 1) cp_wait<1>();
        else                cp_wait<0>();
        __syncthreads();                    // B[s] visible; ring slot (s+2)%3 free
        if (s + 2 < NSTAGE) { cpB(s + 2); cp_commit(); }

        u32 ah0[4], ah1[4];
        {
            const u32 ad = sb + a_row * 512
                         + ((((u32)(4 * s + a_khalf)) ^ (a_row & 7)) << 4);
            ldsm4(ah0, ad);        // k 0..15 of stage
            ldsm4(ah1, ad ^ 32);   // k 16..31
        }
        const u32 bbase = sb + SM_B + (s % 3) * 32768;
        #pragma unroll
        for (int p = 0; p < 4; p++) {
            u32 b0[4], b1[4];
            ldsm4(b0, bbase + offB[p]);          // k 0..15
            ldsm4(b1, (bbase + offB[p]) ^ 32);   // k 16..31
            #pragma unroll
            for (int e = 0; e < 2; e++) {
                float* dd = d[p * 2 + e];
                mma16816(dd, ah0, &b0[2 * e]);
                mma16816(dd, ah1, &b1[2 * e]);
            }
        }
    }

    // ---- epilogue: acc -> smem h[64][520] ----
    __syncthreads();
    float* hb = (float*)smem;
    #pragma unroll
    for (int j = 0; j < 8; j++) {
        const int row = wr * 16 + (lane >> 2);
        const int col = wc * 64 + j * 8 + (lane & 3) * 2;
        *(float2*)&hb[row * HSTRIDE + col]       = make_float2(d[j][0], d[j][1]);
        *(float2*)&hb[(row + 8) * HSTRIDE + col] = make_float2(d[j][2], d[j][3]);
    }
    __syncthreads();

    // ---- streaming warp-row LN + ReLU: 32 warps x 2 rows = 64 ----
    #pragma unroll
    for (int r = 0; r < 2; r++) {
        const int row = w * 2 + r;
        float s = 0.f, sq = 0.f;
        #pragma unroll
        for (int j = 0; j < 4; j++) {
            const int col = lane * 4 + 128 * j;
            const float4 v = *(const float4*)&hb[row * HSTRIDE + col];
            const float4 b = *(const float4*)&bias[col];
            const float h0 = v.x + b.x, h1 = v.y + b.y, h2 = v.z + b.z, h3 = v.w + b.w;
            s  += h0 + h1 + h2 + h3;
            sq += h0 * h0 + h1 * h1 + h2 * h2 + h3 * h3;
        }
        #pragma unroll
        for (int o = 16; o > 0; o >>= 1) {
            s  += __shfl_xor_sync(0xFFFFFFFFu, s,  o);
            sq += __shfl_xor_sync(0xFFFFFFFFu, sq, o);
        }
        const float mu   = s * (1.0f / NDIM);
        const float var  = sq * (1.0f / NDIM) - mu * mu;
        const float rstd = rsqrtf(var + LN_EPS);
        const size_t orow = (size_t)(m0 + row) * NDIM;
        #pragma unroll
        for (int j = 0; j < 4; j++) {
            const int col = lane * 4 + 128 * j;
            const float4 v = *(const float4*)&hb[row * HSTRIDE + col];
            const float4 b = *(const float4*)&bias[col];
            const float4 g = *(const float4*)&gamma[col];
            const float4 z = *(const float4*)&beta[col];
            float4 y;
            y.x = fmaxf((v.x + b.x - mu) * rstd * g.x + z.x, 0.0f);
            y.y = fmaxf((v.y + b.y - mu) * rstd * g.y + z.y, 0.0f);
            y.z = fmaxf((v.z + b.z - mu) * rstd * g.z + z.z, 0.0f);
            y.w = fmaxf((v.w + b.w - mu) * rstd * g.w + z.w, 0.0f);
            *(float4*)&out[orow + col] = y;
        }
    }
}

extern "C" void kernel_launch(void* const* d_in, const int* in_sizes, int n_in,
                              void* d_out, int out_size) {
    const float* emb   = (const float*)d_in[0];
    const float* W_enc = (const float*)d_in[3];
    const float* b_enc = (const float*)d_in[4];
    const float* gamma = (const float*)d_in[5];
    const float* beta  = (const float*)d_in[6];
    float* out = (float*)d_out;

    cudaFuncSetAttribute(gemm_ln_mma,
                         cudaFuncAttributeMaxDynamicSharedMemorySize, SMEM_TOTAL);

    prep_w<<<128, 256>>>(W_enc);

    const int M = in_sizes[0] / DROW;       // 16384
    gemm_ln_mma<<<M / BM, THREADS, SMEM_TOTAL>>>(emb, b_enc, gamma, beta, out);
}

// round 10
// speedup vs baseline: 1.3101x; 1.3101x over previous
#include <cuda_runtime.h>
#include <cuda_fp16.h>
#include <cstdint>

// out = ReLU(LayerNorm(emb[:, :, :256] @ W_enc + b_enc) * gamma + beta)
// (reference kNN/gather path is a provable no-op: pooled == embeddings)
//
// R10: fp16 mma.sync, barrier-free mainloop. 512 thr / 16 warps; each warp owns
// a 64x32 tile (rows = whole CTA tile, 32 private N-columns) and streams its own
// B strip through a warp-private 4-deep cp.async ring. No __syncthreads between
// k-stages; warps self-sync with per-thread cp.async.wait_group.

#define KDIM    256
#define NDIM    512
#define DROW    512
#define BM      64
#define THREADS 512
#define NSTAGE  8           // K / 32
#define LN_EPS  1e-5f

typedef uint32_t u32;

// prepped W: [n][k] fp16 (256 KB, L2-resident)
__device__ __half g_Wh[NDIM * KDIM];

// ---- smem layout (bytes) ----
// A [64][256] fp16 swizzled (row stride 512B) : 0      .. 32767
// B rings: 16 warps x 4 stages x 2KB          : 32768  .. 163839
// epilogue reuses [0..133119] as h[64][520] f32
#define SM_B       32768
#define SMEM_TOTAL 163840
#define HSTRIDE    520

__device__ __forceinline__ u32 smem_u32(const void* p) {
    u32 a;
    asm("{ .reg .u64 t; cvta.to.shared.u64 t, %1; cvt.u32.u64 %0, t; }" : "=r"(a) : "l"(p));
    return a;
}
__device__ __forceinline__ void cp16(u32 dst, const void* src) {
    asm volatile("cp.async.cg.shared.global [%0], [%1], 16;" :: "r"(dst), "l"(src));
}
__device__ __forceinline__ void cp_commit() { asm volatile("cp.async.commit_group;"); }
template <int N>
__device__ __forceinline__ void cp_wait() { asm volatile("cp.async.wait_group %0;" :: "n"(N)); }

__device__ __forceinline__ void ldsm4(u32* r, u32 addr) {
    asm volatile("ldmatrix.sync.aligned.m8n8.x4.shared.b16 {%0,%1,%2,%3}, [%4];"
                 : "=r"(r[0]), "=r"(r[1]), "=r"(r[2]), "=r"(r[3]) : "r"(addr));
}
__device__ __forceinline__ void mma16816(float* d, const u32* a, const u32* b) {
    asm volatile(
        "mma.sync.aligned.m16n8k16.row.col.f32.f16.f16.f32 "
        "{%0,%1,%2,%3}, {%4,%5,%6,%7}, {%8,%9}, {%0,%1,%2,%3};"
        : "+f"(d[0]), "+f"(d[1]), "+f"(d[2]), "+f"(d[3])
        : "r"(a[0]), "r"(a[1]), "r"(a[2]), "r"(a[3]), "r"(b[0]), "r"(b[1]));
}

// ---------------- prep: W [k][n] f32 -> g_Wh [n][k] fp16 ----------------
__global__ void prep_w(const float* __restrict__ W) {
    const int idx = blockIdx.x * blockDim.x + threadIdx.x;   // 0..32767
    const int n  = idx & 511;
    const int k4 = idx >> 9;                                  // 0..63
    unsigned short h[4];
    #pragma unroll
    for (int e = 0; e < 4; e++) {
        const float w = W[(size_t)(k4 * 4 + e) * NDIM + n];   // coalesced over n
        h[e] = __half_as_ushort(__float2half_rn(w));
    }
    *(uint2*)&g_Wh[(size_t)n * KDIM + k4 * 4] =
        make_uint2((u32)h[0] | ((u32)h[1] << 16), (u32)h[2] | ((u32)h[3] << 16));
}

// ---------------- main fused GEMM + LN + ReLU ----------------
__global__ __launch_bounds__(THREADS, 1)
void gemm_ln_mma(const float* __restrict__ emb,
                 const float* __restrict__ bias,
                 const float* __restrict__ gamma,
                 const float* __restrict__ beta,
                 float* __restrict__ out) {
    extern __shared__ char smem[];
    const u32 sb   = smem_u32(smem);
    const int tid  = threadIdx.x;
    const int lane = tid & 31;
    const int w    = tid >> 5;       // 16 warps; warp owns cols w*32..w*32+31
    const int m0   = blockIdx.x * BM;
    const u32 wbase = sb + SM_B + w * 8192;          // warp-private 4-stage ring

    // ---- warp-private B strip loader: 32 n x 64B per stage, 4 cp16/lane ----
    // src: g_Wh[n0+nl][k = 32s + 8cb..], dst swizzled (cb ^ ((nl>>1)&3))
    const int n0 = w * 32;
    auto cpB = [&](int s) {
        const u32 bst = wbase + (s & 3) * 2048;
        #pragma unroll
        for (int j = 0; j < 4; j++) {
            const int i  = lane + 32 * j;      // 0..127
            const int nl = i >> 2;
            const int cb = i & 3;
            cp16(bst + nl * 64 + (((u32)cb ^ ((nl >> 1) & 3)) << 4),
                 (const char*)g_Wh + (size_t)(n0 + nl) * 512 + s * 64 + cb * 16);
        }
        cp_commit();
    };

    cpB(0); cpB(1); cpB(2);

    // ---- A: load 64x256 f32, convert to fp16 into swizzled smem (cooperative) ----
    #pragma unroll
    for (int i = 0; i < 8; i++) {
        const int f   = tid + THREADS * i;    // float4 index, 4096 total
        const int row = f >> 6;
        const int q   = f & 63;               // float4 within row (k = 4q)
        const float4 v = *(const float4*)&emb[(size_t)(m0 + row) * DROW + q * 4];
        const unsigned short h0 = __half_as_ushort(__float2half_rn(v.x));
        const unsigned short h1 = __half_as_ushort(__float2half_rn(v.y));
        const unsigned short h2 = __half_as_ushort(__float2half_rn(v.z));
        const unsigned short h3 = __half_as_ushort(__float2half_rn(v.w));
        const u32 addr = sb + row * 512 + ((((u32)(q >> 1)) ^ (row & 7)) << 4) + (q & 1) * 8;
        asm volatile("st.shared.v2.b32 [%0], {%1, %2};" :: "r"(addr),
                     "r"((u32)h0 | ((u32)h1 << 16)), "r"((u32)h2 | ((u32)h3 << 16)));
    }
    __syncthreads();     // A visible to all; only sync before the epilogue one

    // ---- per-lane ldmatrix geometry ----
    // A frag (m16k16): row = mt*16 + ((lane>>3)&1)*8 + (lane&7); chunk = 4s + (lane>>4)
    const int a_row  = ((lane >> 3) & 1) * 8 + (lane & 7);
    const int a_kh   = lane >> 4;
    // B frag: nl = p*16 + ((lane>>4)&1)*8 + (lane&7), cb = khalf*2 + ((lane>>3)&1)
    u32 offB[2];
    #pragma unroll
    for (int p = 0; p < 2; p++) {
        const int nl = p * 16 + ((lane >> 4) & 1) * 8 + (lane & 7);
        const int cb = (lane >> 3) & 1;
        offB[p] = nl * 64 + (((u32)cb ^ ((nl >> 1) & 3)) << 4);
    }

    float d[4][4][4];    // [mt 16-row tile][n8 tile][frag]
    #pragma unroll
    for (int mt = 0; mt < 4; mt++)
        #pragma unroll
        for (int j = 0; j < 4; j++)
            #pragma unroll
            for (int e = 0; e < 4; e++) d[mt][j][e] = 0.0f;

    // ---- barrier-free mainloop: 8 k32-stages, warp-private ring ----
    #pragma unroll 1
    for (int s = 0; s < NSTAGE; s++) {
        if (s <= NSTAGE - 3)      cp_wait<2>();   // stage s landed (s+1, s+2 in flight)
        else if (s == NSTAGE - 2) cp_wait<1>();
        else                      cp_wait<0>();

        const u32 bst = wbase + (s & 3) * 2048;
        #pragma unroll
        for (int kh = 0; kh < 2; kh++) {          // k-halves of the 32-k stage
            u32 bf[2][4];
            ldsm4(bf[0], (bst + offB[0]) ^ (kh ? 32u : 0u));
            ldsm4(bf[1], (bst + offB[1]) ^ (kh ? 32u : 0u));
            #pragma unroll
            for (int mt = 0; mt < 4; mt++) {
                u32 af[4];
                const int row = a_row + mt * 16;
                const u32 ad = sb + row * 512
                             + ((((u32)(4 * s + a_kh)) ^ (row & 7)) << 4);
                ldsm4(af, ad ^ (kh ? 32u : 0u));
                #pragma unroll
                for (int p = 0; p < 2; p++)
                    #pragma unroll
                    for (int e = 0; e < 2; e++)
                        mma16816(d[mt][p * 2 + e], af, &bf[p][2 * e]);
            }
        }
        if (s + 3 < NSTAGE) cpB(s + 3);   // slot (s+3)&3 == (s-1)&3, done last iter
    }

    // ---- epilogue: acc -> smem h[64][520] ----
    __syncthreads();     // all warps done with A/B smem; safe to overwrite as hb
    float* hb = (float*)smem;
    #pragma unroll
    for (int mt = 0; mt < 4; mt++)
        #pragma unroll
        for (int j = 0; j < 4; j++) {
            const int row = mt * 16 + (lane >> 2);
            const int col = w * 32 + j * 8 + (lane & 3) * 2;
            *(float2*)&hb[row * HSTRIDE + col]       = make_float2(d[mt][j][0], d[mt][j][1]);
            *(float2*)&hb[(row + 8) * HSTRIDE + col] = make_float2(d[mt][j][2], d[mt][j][3]);
        }
    __syncthreads();

    // ---- warp-row LN + ReLU: 16 warps x 4 rows ----
    #pragma unroll
    for (int r = 0; r < 4; r++) {
        const int row = w * 4 + r;
        float s = 0.f, sq = 0.f;
        #pragma unroll
        for (int j = 0; j < 4; j++) {
            const int col = lane * 4 + 128 * j;
            const float4 v = *(const float4*)&hb[row * HSTRIDE + col];
            const float4 b = *(const float4*)&bias[col];
            const float h0 = v.x + b.x, h1 = v.y + b.y, h2 = v.z + b.z, h3 = v.w + b.w;
            s  += h0 + h1 + h2 + h3;
            sq += h0 * h0 + h1 * h1 + h2 * h2 + h3 * h3;
        }
        #pragma unroll
        for (int o = 16; o > 0; o >>= 1) {
            s  += __shfl_xor_sync(0xFFFFFFFFu, s,  o);
            sq += __shfl_xor_sync(0xFFFFFFFFu, sq, o);
        }
        const float mu   = s * (1.0f / NDIM);
        const float var  = sq * (1.0f / NDIM) - mu * mu;
        const float rstd = rsqrtf(var + LN_EPS);
        const size_t orow = (size_t)(m0 + row) * NDIM;
        #pragma unroll
        for (int j = 0; j < 4; j++) {
            const int col = lane * 4 + 128 * j;
            const float4 v = *(const float4*)&hb[row * HSTRIDE + col];
            const float4 b = *(const float4*)&bias[col];
            const float4 g = *(const float4*)&gamma[col];
            const float4 z = *(const float4*)&beta[col];
            float4 y;
            y.x = fmaxf((v.x + b.x - mu) * rstd * g.x + z.x, 0.0f);
            y.y = fmaxf((v.y + b.y - mu) * rstd * g.y + z.y, 0.0f);
            y.z = fmaxf((v.z + b.z - mu) * rstd * g.z + z.z, 0.0f);
            y.w = fmaxf((v.w + b.w - mu) * rstd * g.w + z.w, 0.0f);
            *(float4*)&out[orow + col] = y;
        }
    }
}

extern "C" void kernel_launch(void* const* d_in, const int* in_sizes, int n_in,
                              void* d_out, int out_size) {
    const float* emb   = (const float*)d_in[0];
    const float* W_enc = (const float*)d_in[3];
    const float* b_enc = (const float*)d_in[4];
    const float* gamma = (const float*)d_in[5];
    const float* beta  = (const float*)d_in[6];
    float* out = (float*)d_out;

    cudaFuncSetAttribute(gemm_ln_mma,
                         cudaFuncAttributeMaxDynamicSharedMemorySize, SMEM_TOTAL);

    prep_w<<<128, 256>>>(W_enc);

    const int M = in_sizes[0] / DROW;       // 16384
    gemm_ln_mma<<<M / BM, THREADS, SMEM_TOTAL>>>(emb, b_enc, gamma, beta, out);
}

// round 14
// speedup vs baseline: 1.3226x; 1.0095x over previous
#include <cuda_runtime.h>
#include <cuda_fp16.h>
#include <cstdint>

// out = ReLU(LayerNorm(emb[:, :, :256] @ W_enc + b_enc) * gamma + beta)
// (reference kNN/gather path is a provable no-op: pooled == embeddings)
//
// R12 = R11 resubmitted (previous bench failed on infra, kernel never measured).
// B matrix pre-packed in m16n8k16 fragment order -> loaded straight into
// registers with LDG.128 (L2-resident, 256KB), double-buffered one stage ahead.
// No B smem, no cp.async, barrier-free mainloop. A via smem ldsm (batched).

#define KDIM    256
#define NDIM    512
#define DROW    512
#define BM      64
#define THREADS 512
#define NSTAGE  8           // K / 32
#define LN_EPS  1e-5f

typedef uint32_t u32;

// B fragments: [w 16][s 8][j 4][lane 32][4 x u32]  = 256 KB, L2-resident.
// reg q of (w,s,j,lane): kh=q>>1, rr=q&1 -> f16x2 = W[k][n],W[k+1][n]
//   n = w*32 + j*8 + lane/4,  k = s*32 + kh*16 + (lane%4)*2 + rr*8
__device__ u32 g_Wfrag[16 * 8 * 4 * 32 * 4];

// ---- smem: A [64][256] fp16 swizzled (32KB); epilogue reuses as h[64][520] f32 ----
#define SMEM_TOTAL 133120
#define HSTRIDE    520

__device__ __forceinline__ u32 smem_u32(const void* p) {
    u32 a;
    asm("{ .reg .u64 t; cvta.to.shared.u64 t, %1; cvt.u32.u64 %0, t; }" : "=r"(a) : "l"(p));
    return a;
}
__device__ __forceinline__ void ldsm4(u32* r, u32 addr) {
    asm volatile("ldmatrix.sync.aligned.m8n8.x4.shared.b16 {%0,%1,%2,%3}, [%4];"
                 : "=r"(r[0]), "=r"(r[1]), "=r"(r[2]), "=r"(r[3]) : "r"(addr));
}
__device__ __forceinline__ void mma16816(float* d, const u32* a, const u32* b) {
    asm volatile(
        "mma.sync.aligned.m16n8k16.row.col.f32.f16.f16.f32 "
        "{%0,%1,%2,%3}, {%4,%5,%6,%7}, {%8,%9}, {%0,%1,%2,%3};"
        : "+f"(d[0]), "+f"(d[1]), "+f"(d[2]), "+f"(d[3])
        : "r"(a[0]), "r"(a[1]), "r"(a[2]), "r"(a[3]), "r"(b[0]), "r"(b[1]));
}

// ---------------- prep: W [k][n] f32 -> g_Wfrag (fragment order, fp16) ----------------
__global__ void prep_wfrag(const float* __restrict__ W) {
    const int t    = blockIdx.x * blockDim.x + threadIdx.x;   // 0..16383
    const int lane = t & 31;
    const int j    = (t >> 5) & 3;
    const int s    = (t >> 7) & 7;
    const int w    = t >> 10;
    const int n     = w * 32 + j * 8 + (lane >> 2);
    const int kbase = s * 32 + (lane & 3) * 2;
    u32 r[4];
    #pragma unroll
    for (int q = 0; q < 4; q++) {
        const int k = kbase + (q >> 1) * 16 + (q & 1) * 8;
        const unsigned short h0 = __half_as_ushort(__float2half_rn(W[(size_t)k * NDIM + n]));
        const unsigned short h1 = __half_as_ushort(__float2half_rn(W[(size_t)(k + 1) * NDIM + n]));
        r[q] = (u32)h0 | ((u32)h1 << 16);
    }
    *(uint4*)&g_Wfrag[(size_t)t * 4] = make_uint4(r[0], r[1], r[2], r[3]);
}

// ---------------- main fused GEMM + LN + ReLU ----------------
__global__ __launch_bounds__(THREADS, 1)
void gemm_ln_mma(const float* __restrict__ emb,
                 const float* __restrict__ bias,
                 const float* __restrict__ gamma,
                 const float* __restrict__ beta,
                 float* __restrict__ out) {
    extern __shared__ char smem[];
    const u32 sb   = smem_u32(smem);
    const int tid  = threadIdx.x;
    const int lane = tid & 31;
    const int w    = tid >> 5;       // 16 warps; warp owns cols w*32..w*32+31
    const int m0   = blockIdx.x * BM;

    // B fragment source for this warp: slot j at src[j*32], lane-offset folded in
    const uint4* __restrict__ bsrc = (const uint4*)g_Wfrag + (size_t)w * (8 * 4 * 32) + lane;

    u32 bufA[4][4], bufB[4][4];      // two stage buffers [j][q]
    #pragma unroll
    for (int j = 0; j < 4; j++) {    // prefetch stage 0
        const uint4 v = bsrc[j * 32];
        bufA[j][0] = v.x; bufA[j][1] = v.y; bufA[j][2] = v.z; bufA[j][3] = v.w;
    }

    // ---- A: load 64x256 f32, convert fp16 into swizzled smem (cooperative) ----
    #pragma unroll
    for (int i = 0; i < 8; i++) {
        const int f   = tid + THREADS * i;    // float4 index, 4096 total
        const int row = f >> 6;
        const int q   = f & 63;
        const float4 v = *(const float4*)&emb[(size_t)(m0 + row) * DROW + q * 4];
        const unsigned short h0 = __half_as_ushort(__float2half_rn(v.x));
        const unsigned short h1 = __half_as_ushort(__float2half_rn(v.y));
        const unsigned short h2 = __half_as_ushort(__float2half_rn(v.z));
        const unsigned short h3 = __half_as_ushort(__float2half_rn(v.w));
        const u32 addr = sb + row * 512 + ((((u32)(q >> 1)) ^ (row & 7)) << 4) + (q & 1) * 8;
        asm volatile("st.shared.v2.b32 [%0], {%1, %2};" :: "r"(addr),
                     "r"((u32)h0 | ((u32)h1 << 16)), "r"((u32)h2 | ((u32)h3 << 16)));
    }
    __syncthreads();     // A visible; only other sync is before epilogue smem reuse

    // ---- per-lane A ldsm geometry ----
    const int a_row = ((lane >> 3) & 1) * 8 + (lane & 7);
    const int a_kh  = lane >> 4;
    const int a_swz = a_row & 7;
    u32 aBase[4];
    #pragma unroll
    for (int mt = 0; mt < 4; mt++) aBase[mt] = sb + (a_row + mt * 16) * 512;

    float d[4][4][4];    // [mt][j n8-block][frag]
    #pragma unroll
    for (int mt = 0; mt < 4; mt++)
        #pragma unroll
        for (int j = 0; j < 4; j++)
            #pragma unroll
            for (int e = 0; e < 4; e++) d[mt][j][e] = 0.0f;

    // ---- barrier-free mainloop, fully unrolled (static buffer selection) ----
    #pragma unroll
    for (int s = 0; s < NSTAGE; s++) {
        u32 (&cur)[4][4]  = (s & 1) ? bufB : bufA;
        u32 (&next)[4][4] = (s & 1) ? bufA : bufB;
        if (s + 1 < NSTAGE) {
            const uint4* __restrict__ ns = bsrc + (size_t)(s + 1) * (4 * 32);
            #pragma unroll
            for (int j = 0; j < 4; j++) {
                const uint4 v = ns[j * 32];
                next[j][0] = v.x; next[j][1] = v.y; next[j][2] = v.z; next[j][3] = v.w;
            }
        }
        const u32 phys0 = (((u32)(4 * s + a_kh)) ^ (u32)a_swz) << 4;
        #pragma unroll
        for (int kh = 0; kh < 2; kh++) {
            const u32 poff = kh ? (phys0 ^ 32u) : phys0;
            u32 af[4][4];
            #pragma unroll
            for (int mt = 0; mt < 4; mt++) ldsm4(af[mt], aBase[mt] + poff);
            #pragma unroll
            for (int mt = 0; mt < 4; mt++)
                #pragma unroll
                for (int j = 0; j < 4; j++)
                    mma16816(d[mt][j], af[mt], &cur[j][kh * 2]);
        }
    }

    // ---- epilogue: acc -> smem h[64][520] ----
    __syncthreads();     // all warps done with A smem; safe to overwrite as hb
    float* hb = (float*)smem;
    #pragma unroll
    for (int mt = 0; mt < 4; mt++)
        #pragma unroll
        for (int j = 0; j < 4; j++) {
            const int row = mt * 16 + (lane >> 2);
            const int col = w * 32 + j * 8 + (lane & 3) * 2;
            *(float2*)&hb[row * HSTRIDE + col]       = make_float2(d[mt][j][0], d[mt][j][1]);
            *(float2*)&hb[(row + 8) * HSTRIDE + col] = make_float2(d[mt][j][2], d[mt][j][3]);
        }
    __syncthreads();

    // ---- warp-row LN + ReLU: 16 warps x 4 rows ----
    #pragma unroll
    for (int r = 0; r < 4; r++) {
        const int row = w * 4 + r;
        float s = 0.f, sq = 0.f;
        #pragma unroll
        for (int j = 0; j < 4; j++) {
            const int col = lane * 4 + 128 * j;
            const float4 v = *(const float4*)&hb[row * HSTRIDE + col];
            const float4 b = *(const float4*)&bias[col];
            const float h0 = v.x + b.x, h1 = v.y + b.y, h2 = v.z + b.z, h3 = v.w + b.w;
            s  += h0 + h1 + h2 + h3;
            sq += h0 * h0 + h1 * h1 + h2 * h2 + h3 * h3;
        }
        #pragma unroll
        for (int o = 16; o > 0; o >>= 1) {
            s  += __shfl_xor_sync(0xFFFFFFFFu, s,  o);
            sq += __shfl_xor_sync(0xFFFFFFFFu, sq, o);
        }
        const float mu   = s * (1.0f / NDIM);
        const float var  = sq * (1.0f / NDIM) - mu * mu;
        const float rstd = rsqrtf(var + LN_EPS);
        const size_t orow = (size_t)(m0 + row) * NDIM;
        #pragma unroll
        for (int j = 0; j < 4; j++) {
            const int col = lane * 4 + 128 * j;
            const float4 v = *(const float4*)&hb[row * HSTRIDE + col];
            const float4 b = *(const float4*)&bias[col];
            const float4 g = *(const float4*)&gamma[col];
            const float4 z = *(const float4*)&beta[col];
            float4 y;
            y.x = fmaxf((v.x + b.x - mu) * rstd * g.x + z.x, 0.0f);
            y.y = fmaxf((v.y + b.y - mu) * rstd * g.y + z.y, 0.0f);
            y.z = fmaxf((v.z + b.z - mu) * rstd * g.z + z.z, 0.0f);
            y.w = fmaxf((v.w + b.w - mu) * rstd * g.w + z.w, 0.0f);
            *(float4*)&out[orow + col] = y;
        }
    }
}

extern "C" void kernel_launch(void* const* d_in, const int* in_sizes, int n_in,
                              void* d_out, int out_size) {
    const float* emb   = (const float*)d_in[0];
    const float* W_enc = (const float*)d_in[3];
    const float* b_enc = (const float*)d_in[4];
    const float* gamma = (const float*)d_in[5];
    const float* beta  = (const float*)d_in[6];
    float* out = (float*)d_out;

    cudaFuncSetAttribute(gemm_ln_mma,
                         cudaFuncAttributeMaxDynamicSharedMemorySize, SMEM_TOTAL);

    prep_wfrag<<<64, 256>>>(W_enc);

    const int M = in_sizes[0] / DROW;       // 16384
    gemm_ln_mma<<<M / BM, THREADS, SMEM_TOTAL>>>(emb, b_enc, gamma, beta, out);
}